// round 14
// baseline (speedup 1.0000x reference)
#include <cuda_runtime.h>
#include <cuda_bf16.h>
#include <math.h>

// Problem constants
#define BATCH 2
#define NPTS  4096
#define NG    (BATCH*NPTS)     // 8192 nodes total
#define DIM   128
#define MDIM  16
#define KNN_K 32
#define EH    530              // edge hidden dim (2*265)
#define EHP   544              // padded to 34*16
#define NSTEP 34               // k-tiles of 16
#define NODE_IN 144            // DIM + MDIM
#define NODE_H  256
#define NPB   4                // nodes per edge-kernel block (1 warp each)

// -------------------- scratch (static device globals; no allocation) ----------
__device__ float d_A [NG * EHP];      // feats @ We1[0:128] + be1   (cols 530..543 stay 0)
__device__ float d_Bf[NG * EHP];      // feats @ We1[128:256]       (cols 530..543 stay 0)
__device__ int   d_idx[NG * KNN_K];
__device__ float d_mi [NG * MDIM];
__device__ float d_h  [NG * NODE_H];
__device__ unsigned d_We2frag[NSTEP * 32 * 4];  // bf16 B-fragments (layer 2)
__device__ unsigned d_W1ffrag[NSTEP * 32 * 4];  // bf16 B-fragments (fourier layer 1)
__device__ uint2    d_Wc1frag[8 * 32];          // bf16 B-fragments (coors layer 1)
// packed-transposed bf16 weights for gemm_mma: [n][k/2] u32 (zero-padded)
__device__ unsigned d_WP0[576 * 64];            // We1[0:128]   -> N=530(576), K=128
__device__ unsigned d_WP1[576 * 64];            // We1[128:256] -> N=530(576), K=128
__device__ unsigned d_WP2[256 * 80];            // Wn1: N=256, K=144 (K2P=80)
__device__ unsigned d_WP3[128 * 128];           // Wn2: N=128, K=256

__device__ __forceinline__ float siluf(float x) {
    return x / (1.0f + __expf(-x));
}
__device__ __forceinline__ float silu_fast(float x) {
    float xh = 0.5f * x;
    float t; asm("tanh.approx.f32 %0, %1;" : "=f"(t) : "f"(xh));
    return fmaf(xh, t, xh);
}

// ---------------- packed f32x2 helpers ------------------------------------------
__device__ __forceinline__ unsigned long long pk2(float lo, float hi) {
    unsigned long long r; asm("mov.b64 %0, {%1,%2};" : "=l"(r) : "f"(lo), "f"(hi)); return r;
}
__device__ __forceinline__ void upk2(unsigned long long v, float &lo, float &hi) {
    asm("mov.b64 {%0,%1}, %2;" : "=f"(lo), "=f"(hi) : "l"(v));
}
__device__ __forceinline__ unsigned long long add2(unsigned long long a,
                                                   unsigned long long b) {
    unsigned long long d;
    asm("add.rn.f32x2 %0, %1, %2;" : "=l"(d) : "l"(a), "l"(b));
    return d;
}
// bf16x2 pack: lo -> d[15:0], hi -> d[31:16]
__device__ __forceinline__ unsigned cvtbf2(float lo, float hi) {
    unsigned r; asm("cvt.rn.bf16x2.f32 %0, %1, %2;" : "=r"(r) : "f"(hi), "f"(lo)); return r;
}

#define MMA_BF16(d0,d1,d2,d3,a0,a1,a2,a3,b0,b1) \
    asm("mma.sync.aligned.m16n8k16.row.col.f32.bf16.bf16.f32 " \
        "{%0,%1,%2,%3},{%4,%5,%6,%7},{%8,%9},{%0,%1,%2,%3};" \
        : "+f"(d0),"+f"(d1),"+f"(d2),"+f"(d3) \
        : "r"(a0),"r"(a1),"r"(a2),"r"(a3),"r"(b0),"r"(b1))

// ---------------------- single prep kernel: all packed tables ------------------
__global__ void prep_kernel(const float* __restrict__ We1,
                            const float* __restrict__ We2,
                            const float* __restrict__ Wc1,
                            const float* __restrict__ Wn1,
                            const float* __restrict__ Wn2)
{
    const int i = blockIdx.x * blockDim.x + threadIdx.x;
    if (i < NSTEP * 32) {
        const int s = i >> 5, l = i & 31;
        const int q = l & 3, c0 = l >> 2;
        {   // We2 fragments (layer 2)
            const int k0 = s * 16 + q * 4;
            float v0 = (k0+0 < EH) ? We2[(k0+0)*16 + c0] : 0.f;
            float v1 = (k0+1 < EH) ? We2[(k0+1)*16 + c0] : 0.f;
            float v2 = (k0+2 < EH) ? We2[(k0+2)*16 + c0] : 0.f;
            float v3 = (k0+3 < EH) ? We2[(k0+3)*16 + c0] : 0.f;
            float w0 = (k0+0 < EH) ? We2[(k0+0)*16 + c0+8] : 0.f;
            float w1 = (k0+1 < EH) ? We2[(k0+1)*16 + c0+8] : 0.f;
            float w2 = (k0+2 < EH) ? We2[(k0+2)*16 + c0+8] : 0.f;
            float w3 = (k0+3 < EH) ? We2[(k0+3)*16 + c0+8] : 0.f;
            d_We2frag[i*4+0] = cvtbf2(v0, v1);
            d_We2frag[i*4+1] = cvtbf2(v2, v3);
            d_We2frag[i*4+2] = cvtbf2(w0, w1);
            d_We2frag[i*4+3] = cvtbf2(w2, w3);
        }
        {   // W1f fragments (layer 1)
            const int rk0 = 4*(c0 >> 1) + (c0 & 1);
            const int ka = s*16 + rk0, kb = ka + 2;
            const int f0 = 4*q, f1 = 4*q+1, f2 = 4*q+2, f3 = 4*q+3;
            #define W1F(f,k) (((f) < 9 && (k) < EH) ? We1[(256+(f))*EH + (k)] : 0.f)
            d_W1ffrag[i*4+0] = cvtbf2(W1F(f0,ka), W1F(f1,ka));
            d_W1ffrag[i*4+1] = cvtbf2(W1F(f2,ka), W1F(f3,ka));
            d_W1ffrag[i*4+2] = cvtbf2(W1F(f0,kb), W1F(f1,kb));
            d_W1ffrag[i*4+3] = cvtbf2(W1F(f2,kb), W1F(f3,kb));
            #undef W1F
        }
    }
    if (i < 8 * 32) {   // Wc1 fragments (coors layer 1)
        const int nt = i >> 5, l = i & 31;
        const int q = l & 3, c = l >> 2;
        const int col = nt*8 + c;
        d_Wc1frag[i].x = cvtbf2(Wc1[(2*q  )*64 + col], Wc1[(2*q+1)*64 + col]);
        d_Wc1frag[i].y = cvtbf2(Wc1[(2*q+8)*64 + col], Wc1[(2*q+9)*64 + col]);
    }
    if (i < 576 * 64) {   // WP0 / WP1 (We1 halves): K=128, N=530, ldw=EH
        const int n = i >> 6, j = i & 63;
        const bool ok = (n < EH);
        float lo0 = ok ? We1[(size_t)(2*j  )*EH + n] : 0.f;
        float hi0 = ok ? We1[(size_t)(2*j+1)*EH + n] : 0.f;
        d_WP0[i] = cvtbf2(lo0, hi0);
        float lo1 = ok ? We1[(size_t)(128 + 2*j  )*EH + n] : 0.f;
        float hi1 = ok ? We1[(size_t)(128 + 2*j+1)*EH + n] : 0.f;
        d_WP1[i] = cvtbf2(lo1, hi1);
    }
    if (i < 256 * 80) {   // WP2 (Wn1): K=144, N=256, ldw=NODE_H
        const int n = i / 80, j = i - n * 80;
        float lo = (2*j   < NODE_IN) ? Wn1[(size_t)(2*j  )*NODE_H + n] : 0.f;
        float hi = (2*j+1 < NODE_IN) ? Wn1[(size_t)(2*j+1)*NODE_H + n] : 0.f;
        d_WP2[i] = cvtbf2(lo, hi);
    }
    if (i < 128 * 128) {  // WP3 (Wn2): K=256, N=128, ldw=DIM
        const int n = i >> 7, j = i & 127;
        d_WP3[i] = cvtbf2(Wn2[(size_t)(2*j)*DIM + n], Wn2[(size_t)(2*j+1)*DIM + n]);
    }
}

// ------------------------------ KNN (pair extraction) ---------------------------
// Each round extracts the global min AND second-min: 16 barrier rounds for K=32.
__global__ __launch_bounds__(256) void knn_kernel(const float* __restrict__ coors)
{
    __shared__ unsigned long long keys[256];
    __shared__ unsigned long long keys2[256];
    __shared__ int sj1, sj2;
    const int tid = threadIdx.x;
    const int g = blockIdx.x;
    const int boff = g & ~(NPTS - 1);

    const float cix = coors[g*3+0], ciy = coors[g*3+1], ciz = coors[g*3+2];

    float dv[16];
    #pragma unroll
    for (int s = 0; s < 16; s++) {
        const int j = tid + s*256;
        const int r = boff + j;
        float dx = cix - coors[r*3+0];
        float dy = ciy - coors[r*3+1];
        float dz = ciz - coors[r*3+2];
        dv[s] = dx*dx + dy*dy + dz*dz;
    }
    // local top-2 (lb1 < lb2)
    unsigned long long lb1 = 0xFFFFFFFFFFFFFFFFull, lb2 = 0xFFFFFFFFFFFFFFFFull;
    #pragma unroll
    for (int s = 0; s < 16; s++) {
        unsigned long long key =
            ((unsigned long long)__float_as_uint(dv[s]) << 32) | (unsigned)(tid + s*256);
        if (key < lb1) { lb2 = lb1; lb1 = key; }
        else if (key < lb2) lb2 = key;
    }

    for (int k2 = 0; k2 < KNN_K/2; k2++) {
        keys[tid] = lb1;
        keys2[tid] = lb2;
        __syncthreads();
        if (tid < 32) {
            unsigned long long k8[8];
            #pragma unroll
            for (int o = 0; o < 8; o++) k8[o] = keys[tid + o*32];
            unsigned long long v = k8[0];
            #pragma unroll
            for (int o = 1; o < 8; o++) if (k8[o] < v) v = k8[o];
            #pragma unroll
            for (int off = 16; off; off >>= 1) {
                unsigned long long o = __shfl_xor_sync(0xffffffffu, v, off);
                if (o < v) v = o;
            }
            const unsigned long long w1 = v;   // all lanes
            // second min: substitute owner's slot with its local second
            unsigned long long v2 = 0xFFFFFFFFFFFFFFFFull;
            #pragma unroll
            for (int o = 0; o < 8; o++) {
                unsigned long long t = (k8[o] == w1) ? keys2[tid + o*32] : k8[o];
                if (t < v2) v2 = t;
            }
            #pragma unroll
            for (int off = 16; off; off >>= 1) {
                unsigned long long o = __shfl_xor_sync(0xffffffffu, v2, off);
                if (o < v2) v2 = o;
            }
            if (tid == 0) {
                const int j1 = (int)(w1 & 0xFFFFFFFFull);
                const int j2 = (int)(v2 & 0xFFFFFFFFull);
                sj1 = j1; sj2 = j2;
                d_idx[g*KNN_K + 2*k2    ] = j1;
                d_idx[g*KNN_K + 2*k2 + 1] = j2;
            }
        }
        __syncthreads();
        const int j1 = sj1, j2 = sj2;
        const bool own1 = ((j1 & 255) == tid);
        const bool own2 = ((j2 & 255) == tid);
        if (own1) dv[j1 >> 8] = __int_as_float(0x7F800000);
        if (own2) dv[j2 >> 8] = __int_as_float(0x7F800000);
        if (own1 || own2) {
            lb1 = 0xFFFFFFFFFFFFFFFFull; lb2 = 0xFFFFFFFFFFFFFFFFull;
            #pragma unroll
            for (int s = 0; s < 16; s++) {
                unsigned long long key =
                    ((unsigned long long)__float_as_uint(dv[s]) << 32) | (unsigned)(tid + s*256);
                if (key < lb1) { lb2 = lb1; lb1 = key; }
                else if (key < lb2) lb2 = key;
            }
        }
    }
}

// ------------------------ tensor-core GEMM (bf16 mma, fp32 accum) ---------------
// Y = act( X@W + bias ) + resid.  W pre-packed WP[n][K2P] bf16-pairs.
// Optional X2: A cols >= split read from X2 (row stride ldx2). Optional z-batch:
// blockIdx.z==1 uses WPb/Yb, no bias.
__global__ __launch_bounds__(256) void gemm_mma(
    const float* __restrict__ X, int ldx,
    const float* __restrict__ X2, int ldx2, int split,
    const unsigned* __restrict__ WP, const unsigned* __restrict__ WPb, int K2P,
    const float* __restrict__ bias,
    const float* __restrict__ resid, int ldr,
    float* __restrict__ Y, float* __restrict__ Yb, int ldy,
    int M, int N, int K, int act)
{
    __shared__ unsigned A32[128*20];
    __shared__ unsigned B32[64*20];
    const int tid  = threadIdx.x;
    const int w    = tid >> 5;
    const int lane = tid & 31;
    const int r = lane >> 2, q = lane & 3;
    const int warpM = (w & 3) * 32, warpN = (w >> 2) * 32;
    const int m0 = blockIdx.y * 128, n0 = blockIdx.x * 64;

    const unsigned* wp = WP;
    float* y = Y;
    const float* bi = bias;
    if (blockIdx.z) { wp = WPb; y = Yb; bi = nullptr; }

    float acc[2][4][4];
    #pragma unroll
    for (int mt = 0; mt < 2; mt++)
        #pragma unroll
        for (int nt = 0; nt < 4; nt++)
            #pragma unroll
            for (int e = 0; e < 4; e++) acc[mt][nt][e] = 0.f;

    for (int k0 = 0; k0 < K; k0 += 32) {
        #pragma unroll
        for (int i = 0; i < 4; i++) {
            int idx = tid + i*256;
            int m = idx >> 3, j4 = idx & 7;
            int kk = k0 + j4*4;
            float4 xv = make_float4(0.f, 0.f, 0.f, 0.f);
            if (kk < K) {
                if (!X2 || kk < split)
                    xv = *(const float4*)&X[(size_t)(m0 + m) * ldx + kk];
                else
                    xv = *(const float4*)&X2[(size_t)(m0 + m) * ldx2 + (kk - split)];
            }
            A32[m*20 + j4*2    ] = cvtbf2(xv.x, xv.y);
            A32[m*20 + j4*2 + 1] = cvtbf2(xv.z, xv.w);
        }
        #pragma unroll
        for (int i = 0; i < 4; i++) {
            int idx = tid + i*256;
            int n = idx >> 4, j = idx & 15;
            B32[n*20 + j] = wp[(size_t)(n0 + n) * K2P + (k0 >> 1) + j];
        }
        __syncthreads();
        #pragma unroll
        for (int ks = 0; ks < 2; ks++) {
            unsigned bfr[4][2];
            #pragma unroll
            for (int nt = 0; nt < 4; nt++) {
                bfr[nt][0] = B32[(warpN + nt*8 + r)*20 + ks*8 + q];
                bfr[nt][1] = B32[(warpN + nt*8 + r)*20 + ks*8 + q + 4];
            }
            #pragma unroll
            for (int mt = 0; mt < 2; mt++) {
                const int rowb = (warpM + mt*16 + r)*20 + ks*8 + q;
                unsigned a0 = A32[rowb];
                unsigned a1 = A32[rowb + 8*20];
                unsigned a2 = A32[rowb + 4];
                unsigned a3 = A32[rowb + 8*20 + 4];
                #pragma unroll
                for (int nt = 0; nt < 4; nt++)
                    MMA_BF16(acc[mt][nt][0], acc[mt][nt][1], acc[mt][nt][2], acc[mt][nt][3],
                             a0, a1, a2, a3, bfr[nt][0], bfr[nt][1]);
            }
        }
        __syncthreads();
    }

    #pragma unroll
    for (int mt = 0; mt < 2; mt++) {
        #pragma unroll
        for (int nt = 0; nt < 4; nt++) {
            const int row0 = m0 + warpM + mt*16 + r;
            const int c0 = n0 + warpN + nt*8 + 2*q;
            #pragma unroll
            for (int e = 0; e < 2; e++) {
                int c = c0 + e;
                if (c < N) {
                    float v0 = acc[mt][nt][e];
                    float v1 = acc[mt][nt][e + 2];
                    if (bi)   { float b = bi[c]; v0 += b; v1 += b; }
                    if (act)  { v0 = siluf(v0); v1 = siluf(v1); }
                    if (resid) {
                        v0 += resid[(size_t)row0 * ldr + c];
                        v1 += resid[(size_t)(row0 + 8) * ldr + c];
                    }
                    y[(size_t)row0 * ldy + c]       = v0;
                    y[(size_t)(row0 + 8) * ldy + c] = v1;
                }
            }
        }
    }
}

// ------------- fused edge kernel (triple-chained mma.sync bf16) -----------------
__global__ __launch_bounds__(128, 5) void edge_kernel(
    const float* __restrict__ coors,
    const float* __restrict__ be2,   // 16
    const float* __restrict__ bc1,   // 64
    const float* __restrict__ Wc2,   // 64
    const float* __restrict__ bc2,   // 1
    float* __restrict__ out_coors)   // NG x 3
{
    __shared__ __align__(16) float sA[NPB*EHP];
    __shared__ float sWc2[64];
    __shared__ float sbc1[64];
    __shared__ float sbe2[16];
    __shared__ float sfe[NPB*32*9];
    __shared__ float srel[NPB*32*3];
    __shared__ int   sj[NPB*32];

    const int tid  = threadIdx.x;
    const int w    = tid >> 5;
    const int lane = tid & 31;

    {
        const int g0 = blockIdx.x * NPB;
        for (int i = tid; i < NPB*EHP; i += 128)
            sA[i] = d_A[(size_t)g0*EHP + i];
    }
    if (tid < 64) sWc2[tid] = Wc2[tid];
    if (tid < 64) sbc1[tid] = bc1[tid];
    if (tid < 16) sbe2[tid] = be2[tid];

    const int g = blockIdx.x * NPB + w;
    const int boff = g & ~(NPTS - 1);
    const float cix = coors[g*3+0], ciy = coors[g*3+1], ciz = coors[g*3+2];
    const float bc2v = bc2[0];

    {
        const int j = d_idx[g*KNN_K + lane];
        sj[w*32 + lane] = j;
        const int r = boff + j;
        float rx = cix - coors[r*3+0];
        float ry = ciy - coors[r*3+1];
        float rz = ciz - coors[r*3+2];
        float d  = rx*rx + ry*ry + rz*rz;
        float* fp = sfe + (w*32 + lane)*9;
        float s, c;
        sincosf(d,        &s, &c); fp[0] = s; fp[4] = c;
        sincosf(d*0.5f,   &s, &c); fp[1] = s; fp[5] = c;
        sincosf(d*0.25f,  &s, &c); fp[2] = s; fp[6] = c;
        sincosf(d*0.125f, &s, &c); fp[3] = s; fp[7] = c;
        fp[8] = d;
        float* rp = srel + (w*32 + lane)*3;
        rp[0] = rx; rp[1] = ry; rp[2] = rz;
    }
    __syncthreads();

    const int q  = lane & 3;
    const int E1 = lane >> 2;
    const int E2 = E1 + 8;
    unsigned long long ms0 = 0ull, ms1 = 0ull;
    float cax = 0.f, cay = 0.f, caz = 0.f;

    const float be2a = sbe2[2*q],   be2b = sbe2[2*q+1];
    const float be2c = sbe2[2*q+8], be2d = sbe2[2*q+9];

    #pragma unroll 1
    for (int grp = 0; grp < 2; grp++) {
        const int e0 = grp*16;
        unsigned feA0, feA1, feA2, feA3;
        {
            const float* f1 = sfe + (w*32 + e0 + E1)*9;
            const float* f2 = sfe + (w*32 + e0 + E2)*9;
            const int fq = 4*q;
            float a0 = (fq   < 9) ? f1[fq]   : 0.f;
            float a1 = (fq+1 < 9) ? f1[fq+1] : 0.f;
            float a2 = (fq+2 < 9) ? f1[fq+2] : 0.f;
            float a3 = (fq+3 < 9) ? f1[fq+3] : 0.f;
            float b0 = (fq   < 9) ? f2[fq]   : 0.f;
            float b1 = (fq+1 < 9) ? f2[fq+1] : 0.f;
            float b2 = (fq+2 < 9) ? f2[fq+2] : 0.f;
            float b3 = (fq+3 < 9) ? f2[fq+3] : 0.f;
            feA0 = cvtbf2(a0, a1);
            feA1 = cvtbf2(b0, b1);
            feA2 = cvtbf2(a2, a3);
            feA3 = cvtbf2(b2, b3);
        }
        const float* pB1 = d_Bf + (size_t)(boff + sj[w*32 + e0 + E1]) * EHP;
        const float* pB2 = d_Bf + (size_t)(boff + sj[w*32 + e0 + E2]) * EHP;

        float m00=0.f,m01=0.f,m02=0.f,m03=0.f;
        float m10=0.f,m11=0.f,m12=0.f,m13=0.f;

        ulonglong2 bb1 = *(const ulonglong2*)(pB1 + 4*q);
        ulonglong2 bb2 = *(const ulonglong2*)(pB2 + 4*q);

        #pragma unroll 1
        for (int s = 0; s < NSTEP; s++) {
            const int ka = s*16 + 4*q;
            ulonglong2 nb1, nb2;
            if (s < NSTEP-1) {
                nb1 = *(const ulonglong2*)(pB1 + ka + 16);
                nb2 = *(const ulonglong2*)(pB2 + ka + 16);
            }
            const ulonglong2 aa = *(const ulonglong2*)(sA + w*EHP + ka);
            float d00,d01,d02,d03, u00,u01,u02,u03;
            { unsigned long long t = add2(aa.x, bb1.x); upk2(t, d00, d01); }
            { unsigned long long t = add2(aa.x, bb2.x); upk2(t, d02, d03); }
            { unsigned long long t = add2(aa.y, bb1.y); upk2(t, u00, u01); }
            { unsigned long long t = add2(aa.y, bb2.y); upk2(t, u02, u03); }
            const uint4 wf = *(const uint4*)&d_W1ffrag[(s*32 + lane)*4];
            MMA_BF16(d00,d01,d02,d03, feA0,feA1,feA2,feA3, wf.x, wf.y);
            MMA_BF16(u00,u01,u02,u03, feA0,feA1,feA2,feA3, wf.z, wf.w);
            const unsigned a0 = cvtbf2(silu_fast(d00), silu_fast(d01));
            const unsigned a1 = cvtbf2(silu_fast(d02), silu_fast(d03));
            const unsigned a2 = cvtbf2(silu_fast(u00), silu_fast(u01));
            const unsigned a3 = cvtbf2(silu_fast(u02), silu_fast(u03));
            const uint4 bf = *(const uint4*)&d_We2frag[(s*32 + lane)*4];
            MMA_BF16(m00,m01,m02,m03, a0,a1,a2,a3, bf.x, bf.y);
            MMA_BF16(m10,m11,m12,m13, a0,a1,a2,a3, bf.z, bf.w);
            bb1 = nb1; bb2 = nb2;
        }

        const float s00 = siluf(m00 + be2a), s01 = siluf(m01 + be2b);
        const float s02 = siluf(m02 + be2a), s03 = siluf(m03 + be2b);
        const float s10 = siluf(m10 + be2c), s11 = siluf(m11 + be2d);
        const float s12 = siluf(m12 + be2c), s13 = siluf(m13 + be2d);

        ms0 = add2(ms0, add2(pk2(s00, s01), pk2(s02, s03)));
        ms1 = add2(ms1, add2(pk2(s10, s11), pk2(s12, s13)));

        const unsigned am0 = cvtbf2(s00, s01);
        const unsigned am1 = cvtbf2(s02, s03);
        const unsigned am2 = cvtbf2(s10, s11);
        const unsigned am3 = cvtbf2(s12, s13);
        float wE1 = 0.f, wE2 = 0.f;
        #pragma unroll
        for (int nt = 0; nt < 8; nt++) {
            const uint2 wb = d_Wc1frag[nt*32 + lane];
            float h0=0.f,h1=0.f,h2=0.f,h3=0.f;
            MMA_BF16(h0,h1,h2,h3, am0,am1,am2,am3, wb.x, wb.y);
            const float2 bb = *(const float2*)(sbc1 + nt*8 + 2*q);
            const float2 cc = *(const float2*)(sWc2 + nt*8 + 2*q);
            wE1 += silu_fast(h0 + bb.x)*cc.x + silu_fast(h1 + bb.y)*cc.y;
            wE2 += silu_fast(h2 + bb.x)*cc.x + silu_fast(h3 + bb.y)*cc.y;
        }
        unsigned long long wp = pk2(wE1, wE2);
        wp = add2(wp, __shfl_xor_sync(0xffffffffu, wp, 1));
        wp = add2(wp, __shfl_xor_sync(0xffffffffu, wp, 2));
        float we1, we2; upk2(wp, we1, we2);
        we1 += bc2v; we2 += bc2v;
        if (q == 0) {
            const float* r1 = srel + (w*32 + e0 + E1)*3;
            const float* r2 = srel + (w*32 + e0 + E2)*3;
            cax += we1*r1[0] + we2*r2[0];
            cay += we1*r1[1] + we2*r2[1];
            caz += we1*r1[2] + we2*r2[2];
        }
    }

    ms0 = add2(ms0, __shfl_xor_sync(0xffffffffu, ms0, 4));
    ms0 = add2(ms0, __shfl_xor_sync(0xffffffffu, ms0, 8));
    ms0 = add2(ms0, __shfl_xor_sync(0xffffffffu, ms0, 16));
    ms1 = add2(ms1, __shfl_xor_sync(0xffffffffu, ms1, 4));
    ms1 = add2(ms1, __shfl_xor_sync(0xffffffffu, ms1, 8));
    ms1 = add2(ms1, __shfl_xor_sync(0xffffffffu, ms1, 16));
    if (lane < 4) {
        float lo, hi;
        upk2(ms0, lo, hi);
        d_mi[(size_t)g*MDIM + 2*lane    ] = lo;
        d_mi[(size_t)g*MDIM + 2*lane + 1] = hi;
        upk2(ms1, lo, hi);
        d_mi[(size_t)g*MDIM + 2*lane + 8] = lo;
        d_mi[(size_t)g*MDIM + 2*lane + 9] = hi;
    }

    cax += __shfl_xor_sync(0xffffffffu, cax, 4);
    cax += __shfl_xor_sync(0xffffffffu, cax, 8);
    cax += __shfl_xor_sync(0xffffffffu, cax, 16);
    cay += __shfl_xor_sync(0xffffffffu, cay, 4);
    cay += __shfl_xor_sync(0xffffffffu, cay, 8);
    cay += __shfl_xor_sync(0xffffffffu, cay, 16);
    caz += __shfl_xor_sync(0xffffffffu, caz, 4);
    caz += __shfl_xor_sync(0xffffffffu, caz, 8);
    caz += __shfl_xor_sync(0xffffffffu, caz, 16);
    if (lane == 0) {
        out_coors[g*3+0] = cax + cix;
        out_coors[g*3+1] = cay + ciy;
        out_coors[g*3+2] = caz + ciz;
    }
}

// ------------------------------ launch ----------------------------------------
extern "C" void kernel_launch(void* const* d_in, const int* in_sizes, int n_in,
                              void* d_out, int out_size)
{
    const float* feats = (const float*)d_in[0];
    const float* coors = (const float*)d_in[1];
    const float* We1   = (const float*)d_in[2];
    const float* be1   = (const float*)d_in[3];
    const float* We2   = (const float*)d_in[4];
    const float* be2   = (const float*)d_in[5];
    const float* Wc1   = (const float*)d_in[6];
    const float* bc1   = (const float*)d_in[7];
    const float* Wc2   = (const float*)d_in[8];
    const float* bc2   = (const float*)d_in[9];
    const float* Wn1   = (const float*)d_in[10];
    const float* bn1   = (const float*)d_in[11];
    const float* Wn2   = (const float*)d_in[12];
    const float* bn2   = (const float*)d_in[13];

    float* out_nodes = (float*)d_out;
    float* out_coors = out_nodes + (size_t)NG * DIM;

    float *pA, *pB, *pMI, *pH;
    unsigned *pW0, *pW1, *pW2, *pW3;
    cudaGetSymbolAddress((void**)&pA,  d_A);
    cudaGetSymbolAddress((void**)&pB,  d_Bf);
    cudaGetSymbolAddress((void**)&pMI, d_mi);
    cudaGetSymbolAddress((void**)&pH,  d_h);
    cudaGetSymbolAddress((void**)&pW0, d_WP0);
    cudaGetSymbolAddress((void**)&pW1, d_WP1);
    cudaGetSymbolAddress((void**)&pW2, d_WP2);
    cudaGetSymbolAddress((void**)&pW3, d_WP3);

    // 0. one prep launch for all packed tables
    prep_kernel<<<(576*64 + 255)/256, 256>>>(We1, We2, Wc1, Wn1, Wn2);

    // 1. KNN
    knn_kernel<<<NG, 256>>>(coors);

    // 2. A and B in one z-batched launch
    {
        dim3 grid((EH + 63) / 64, NG / 128, 2);
        gemm_mma<<<grid, 256>>>(feats, DIM, nullptr, 0, 1<<30,
                                pW0, pW1, 64, be1, nullptr, 0,
                                pA, pB, EHP, NG, EH, DIM, 0);
    }

    // 3. fused edge kernel: m_i + coors_out
    edge_kernel<<<NG / NPB, 128>>>(coors, be2, bc1, Wc2, bc2, out_coors);

    // 4. node MLP (nodein fused into the Wn1 gemm via X2/split)
    {
        dim3 g1(NODE_H / 64, NG / 128, 1);
        gemm_mma<<<g1, 256>>>(feats, DIM, pMI, MDIM, DIM,
                              pW2, nullptr, 80, bn1, nullptr, 0,
                              pH, nullptr, NODE_H, NG, NODE_H, NODE_IN, 1);
        dim3 g2(DIM / 64, NG / 128, 1);
        gemm_mma<<<g2, 256>>>(pH, NODE_H, nullptr, 0, 1<<30,
                              pW3, nullptr, 128, bn2, feats, DIM,
                              out_nodes, nullptr, DIM, NG, DIM, NODE_H, 0);
    }
}

// round 15
// speedup vs baseline: 1.2707x; 1.2707x over previous
#include <cuda_runtime.h>
#include <cuda_bf16.h>
#include <math.h>

// Problem constants
#define BATCH 2
#define NPTS  4096
#define NG    (BATCH*NPTS)     // 8192 nodes total
#define DIM   128
#define MDIM  16
#define KNN_K 32
#define EH    530              // edge hidden dim (2*265)
#define EHP   544              // padded to 34*16
#define NSTEP 34               // k-tiles of 16
#define NODE_IN 144            // DIM + MDIM
#define NODE_H  256
#define NPB   4                // nodes per edge-kernel block (1 warp each)

// -------------------- scratch (static device globals; no allocation) ----------
__device__ float d_A [NG * EHP];      // feats @ We1[0:128] + be1   (cols 530..543 stay 0)
__device__ float d_Bf[NG * EHP];      // feats @ We1[128:256]       (cols 530..543 stay 0)
__device__ int   d_idx[NG * KNN_K];
__device__ float d_mi [NG * MDIM];
__device__ float d_nodein[NG * NODE_IN];
__device__ float d_h  [NG * NODE_H];
__device__ unsigned d_We2frag[NSTEP * 32 * 4];  // bf16 B-fragments (layer 2)
__device__ unsigned d_W1ffrag[NSTEP * 32 * 4];  // bf16 B-fragments (fourier layer 1)
__device__ uint2    d_Wc1frag[8 * 32];          // bf16 B-fragments (coors layer 1)
// packed-transposed bf16 weights for gemm_mma: [n][k/2] u32 (zero-padded)
__device__ unsigned d_WP0[576 * 64];            // We1[0:128]   -> N=530(576), K=128
__device__ unsigned d_WP1[576 * 64];            // We1[128:256] -> N=530(576), K=128
__device__ unsigned d_WP2[256 * 80];            // Wn1: N=256, K=144 (K2P=80)
__device__ unsigned d_WP3[128 * 128];           // Wn2: N=128, K=256

__device__ __forceinline__ float siluf(float x) {
    return x / (1.0f + __expf(-x));
}
__device__ __forceinline__ float silu_fast(float x) {
    float xh = 0.5f * x;
    float t; asm("tanh.approx.f32 %0, %1;" : "=f"(t) : "f"(xh));
    return fmaf(xh, t, xh);
}

// ---------------- packed f32x2 helpers ------------------------------------------
__device__ __forceinline__ unsigned long long pk2(float lo, float hi) {
    unsigned long long r; asm("mov.b64 %0, {%1,%2};" : "=l"(r) : "f"(lo), "f"(hi)); return r;
}
__device__ __forceinline__ void upk2(unsigned long long v, float &lo, float &hi) {
    asm("mov.b64 {%0,%1}, %2;" : "=f"(lo), "=f"(hi) : "l"(v));
}
__device__ __forceinline__ unsigned long long add2(unsigned long long a,
                                                   unsigned long long b) {
    unsigned long long d;
    asm("add.rn.f32x2 %0, %1, %2;" : "=l"(d) : "l"(a), "l"(b));
    return d;
}
// bf16x2 pack: lo -> d[15:0], hi -> d[31:16]
__device__ __forceinline__ unsigned cvtbf2(float lo, float hi) {
    unsigned r; asm("cvt.rn.bf16x2.f32 %0, %1, %2;" : "=r"(r) : "f"(hi), "f"(lo)); return r;
}

#define MMA_BF16(d0,d1,d2,d3,a0,a1,a2,a3,b0,b1) \
    asm("mma.sync.aligned.m16n8k16.row.col.f32.bf16.bf16.f32 " \
        "{%0,%1,%2,%3},{%4,%5,%6,%7},{%8,%9},{%0,%1,%2,%3};" \
        : "+f"(d0),"+f"(d1),"+f"(d2),"+f"(d3) \
        : "r"(a0),"r"(a1),"r"(a2),"r"(a3),"r"(b0),"r"(b1))

// ---------------------- single prep kernel: all packed tables ------------------
__global__ void prep_kernel(const float* __restrict__ We1,
                            const float* __restrict__ We2,
                            const float* __restrict__ Wc1,
                            const float* __restrict__ Wn1,
                            const float* __restrict__ Wn2)
{
    const int i = blockIdx.x * blockDim.x + threadIdx.x;
    if (i < NSTEP * 32) {
        const int s = i >> 5, l = i & 31;
        const int q = l & 3, c0 = l >> 2;
        {   // We2 fragments (layer 2)
            const int k0 = s * 16 + q * 4;
            float v0 = (k0+0 < EH) ? We2[(k0+0)*16 + c0] : 0.f;
            float v1 = (k0+1 < EH) ? We2[(k0+1)*16 + c0] : 0.f;
            float v2 = (k0+2 < EH) ? We2[(k0+2)*16 + c0] : 0.f;
            float v3 = (k0+3 < EH) ? We2[(k0+3)*16 + c0] : 0.f;
            float w0 = (k0+0 < EH) ? We2[(k0+0)*16 + c0+8] : 0.f;
            float w1 = (k0+1 < EH) ? We2[(k0+1)*16 + c0+8] : 0.f;
            float w2 = (k0+2 < EH) ? We2[(k0+2)*16 + c0+8] : 0.f;
            float w3 = (k0+3 < EH) ? We2[(k0+3)*16 + c0+8] : 0.f;
            d_We2frag[i*4+0] = cvtbf2(v0, v1);
            d_We2frag[i*4+1] = cvtbf2(v2, v3);
            d_We2frag[i*4+2] = cvtbf2(w0, w1);
            d_We2frag[i*4+3] = cvtbf2(w2, w3);
        }
        {   // W1f fragments (layer 1)
            const int rk0 = 4*(c0 >> 1) + (c0 & 1);
            const int ka = s*16 + rk0, kb = ka + 2;
            const int f0 = 4*q, f1 = 4*q+1, f2 = 4*q+2, f3 = 4*q+3;
            #define W1F(f,k) (((f) < 9 && (k) < EH) ? We1[(256+(f))*EH + (k)] : 0.f)
            d_W1ffrag[i*4+0] = cvtbf2(W1F(f0,ka), W1F(f1,ka));
            d_W1ffrag[i*4+1] = cvtbf2(W1F(f2,ka), W1F(f3,ka));
            d_W1ffrag[i*4+2] = cvtbf2(W1F(f0,kb), W1F(f1,kb));
            d_W1ffrag[i*4+3] = cvtbf2(W1F(f2,kb), W1F(f3,kb));
            #undef W1F
        }
    }
    if (i < 8 * 32) {   // Wc1 fragments (coors layer 1)
        const int nt = i >> 5, l = i & 31;
        const int q = l & 3, c = l >> 2;
        const int col = nt*8 + c;
        d_Wc1frag[i].x = cvtbf2(Wc1[(2*q  )*64 + col], Wc1[(2*q+1)*64 + col]);
        d_Wc1frag[i].y = cvtbf2(Wc1[(2*q+8)*64 + col], Wc1[(2*q+9)*64 + col]);
    }
    if (i < 576 * 64) {   // WP0 / WP1 (We1 halves): K=128, N=530, ldw=EH
        const int n = i >> 6, j = i & 63;
        const bool ok = (n < EH);
        float lo0 = ok ? We1[(size_t)(2*j  )*EH + n] : 0.f;
        float hi0 = ok ? We1[(size_t)(2*j+1)*EH + n] : 0.f;
        d_WP0[i] = cvtbf2(lo0, hi0);
        float lo1 = ok ? We1[(size_t)(128 + 2*j  )*EH + n] : 0.f;
        float hi1 = ok ? We1[(size_t)(128 + 2*j+1)*EH + n] : 0.f;
        d_WP1[i] = cvtbf2(lo1, hi1);
    }
    if (i < 256 * 80) {   // WP2 (Wn1): K=144, N=256, ldw=NODE_H
        const int n = i / 80, j = i - n * 80;
        float lo = (2*j   < NODE_IN) ? Wn1[(size_t)(2*j  )*NODE_H + n] : 0.f;
        float hi = (2*j+1 < NODE_IN) ? Wn1[(size_t)(2*j+1)*NODE_H + n] : 0.f;
        d_WP2[i] = cvtbf2(lo, hi);
    }
    if (i < 128 * 128) {  // WP3 (Wn2): K=256, N=128, ldw=DIM
        const int n = i >> 7, j = i & 127;
        d_WP3[i] = cvtbf2(Wn2[(size_t)(2*j)*DIM + n], Wn2[(size_t)(2*j+1)*DIM + n]);
    }
}

// ------------------------------ KNN (R13 version: single extraction) ------------
__global__ __launch_bounds__(256) void knn_kernel(const float* __restrict__ coors)
{
    __shared__ unsigned long long keys[256];
    __shared__ unsigned long long swin;
    const int tid = threadIdx.x;
    const int g = blockIdx.x;
    const int boff = g & ~(NPTS - 1);

    const float cix = coors[g*3+0], ciy = coors[g*3+1], ciz = coors[g*3+2];

    float dv[16];
    #pragma unroll
    for (int s = 0; s < 16; s++) {
        const int j = tid + s*256;
        const int r = boff + j;
        float dx = cix - coors[r*3+0];
        float dy = ciy - coors[r*3+1];
        float dz = ciz - coors[r*3+2];
        dv[s] = dx*dx + dy*dy + dz*dz;
    }
    unsigned long long lb = 0xFFFFFFFFFFFFFFFFull;
    #pragma unroll
    for (int s = 0; s < 16; s++) {
        unsigned long long key =
            ((unsigned long long)__float_as_uint(dv[s]) << 32) | (unsigned)(tid + s*256);
        if (key < lb) lb = key;
    }

    for (int k = 0; k < KNN_K; k++) {
        keys[tid] = lb;
        __syncthreads();
        if (tid < 32) {
            unsigned long long v = keys[tid];
            #pragma unroll
            for (int o = 1; o < 8; o++) {
                unsigned long long t = keys[tid + o*32];
                if (t < v) v = t;
            }
            #pragma unroll
            for (int off = 16; off; off >>= 1) {
                unsigned long long o = __shfl_xor_sync(0xffffffffu, v, off);
                if (o < v) v = o;
            }
            if (tid == 0) {
                swin = v;
                d_idx[g*KNN_K + k] = (int)(v & 0xFFFFFFFFull);
            }
        }
        __syncthreads();
        const int wj = (int)(swin & 0xFFFFFFFFull);
        if ((wj & 255) == tid) {
            dv[wj >> 8] = __int_as_float(0x7F800000);
            lb = 0xFFFFFFFFFFFFFFFFull;
            #pragma unroll
            for (int s = 0; s < 16; s++) {
                unsigned long long key =
                    ((unsigned long long)__float_as_uint(dv[s]) << 32) | (unsigned)(tid + s*256);
                if (key < lb) lb = key;
            }
        }
    }
}

// ------------------------ tensor-core GEMM (bf16 mma, fp32 accum) ---------------
// Y = act( X@W + bias ) + resid.  W pre-packed WP[n][K2P] bf16-pairs.
// Optional z-batch: blockIdx.z==1 uses WPb/Yb, no bias.
__global__ __launch_bounds__(256) void gemm_mma(
    const float* __restrict__ X, int ldx,
    const unsigned* __restrict__ WP, const unsigned* __restrict__ WPb, int K2P,
    const float* __restrict__ bias,
    const float* __restrict__ resid, int ldr,
    float* __restrict__ Y, float* __restrict__ Yb, int ldy,
    int M, int N, int K, int act)
{
    __shared__ unsigned A32[128*20];
    __shared__ unsigned B32[64*20];
    const int tid  = threadIdx.x;
    const int w    = tid >> 5;
    const int lane = tid & 31;
    const int r = lane >> 2, q = lane & 3;
    const int warpM = (w & 3) * 32, warpN = (w >> 2) * 32;
    const int m0 = blockIdx.y * 128, n0 = blockIdx.x * 64;

    const unsigned* wp = WP;
    float* y = Y;
    const float* bi = bias;
    if (blockIdx.z) { wp = WPb; y = Yb; bi = nullptr; }

    float acc[2][4][4];
    #pragma unroll
    for (int mt = 0; mt < 2; mt++)
        #pragma unroll
        for (int nt = 0; nt < 4; nt++)
            #pragma unroll
            for (int e = 0; e < 4; e++) acc[mt][nt][e] = 0.f;

    for (int k0 = 0; k0 < K; k0 += 32) {
        #pragma unroll
        for (int i = 0; i < 4; i++) {
            int idx = tid + i*256;
            int m = idx >> 3, j4 = idx & 7;
            int kk = k0 + j4*4;
            float4 xv = make_float4(0.f, 0.f, 0.f, 0.f);
            if (kk < K) xv = *(const float4*)&X[(size_t)(m0 + m) * ldx + kk];
            A32[m*20 + j4*2    ] = cvtbf2(xv.x, xv.y);
            A32[m*20 + j4*2 + 1] = cvtbf2(xv.z, xv.w);
        }
        #pragma unroll
        for (int i = 0; i < 4; i++) {
            int idx = tid + i*256;
            int n = idx >> 4, j = idx & 15;
            B32[n*20 + j] = wp[(size_t)(n0 + n) * K2P + (k0 >> 1) + j];
        }
        __syncthreads();
        #pragma unroll
        for (int ks = 0; ks < 2; ks++) {
            unsigned bfr[4][2];
            #pragma unroll
            for (int nt = 0; nt < 4; nt++) {
                bfr[nt][0] = B32[(warpN + nt*8 + r)*20 + ks*8 + q];
                bfr[nt][1] = B32[(warpN + nt*8 + r)*20 + ks*8 + q + 4];
            }
            #pragma unroll
            for (int mt = 0; mt < 2; mt++) {
                const int rowb = (warpM + mt*16 + r)*20 + ks*8 + q;
                unsigned a0 = A32[rowb];
                unsigned a1 = A32[rowb + 8*20];
                unsigned a2 = A32[rowb + 4];
                unsigned a3 = A32[rowb + 8*20 + 4];
                #pragma unroll
                for (int nt = 0; nt < 4; nt++)
                    MMA_BF16(acc[mt][nt][0], acc[mt][nt][1], acc[mt][nt][2], acc[mt][nt][3],
                             a0, a1, a2, a3, bfr[nt][0], bfr[nt][1]);
            }
        }
        __syncthreads();
    }

    #pragma unroll
    for (int mt = 0; mt < 2; mt++) {
        #pragma unroll
        for (int nt = 0; nt < 4; nt++) {
            const int row0 = m0 + warpM + mt*16 + r;
            const int c0 = n0 + warpN + nt*8 + 2*q;
            #pragma unroll
            for (int e = 0; e < 2; e++) {
                int c = c0 + e;
                if (c < N) {
                    float v0 = acc[mt][nt][e];
                    float v1 = acc[mt][nt][e + 2];
                    if (bi)   { float b = bi[c]; v0 += b; v1 += b; }
                    if (act)  { v0 = siluf(v0); v1 = siluf(v1); }
                    if (resid) {
                        v0 += resid[(size_t)row0 * ldr + c];
                        v1 += resid[(size_t)(row0 + 8) * ldr + c];
                    }
                    y[(size_t)row0 * ldy + c]       = v0;
                    y[(size_t)(row0 + 8) * ldy + c] = v1;
                }
            }
        }
    }
}

// ------------- fused edge kernel (triple-chained mma.sync bf16) -----------------
__global__ __launch_bounds__(128, 5) void edge_kernel(
    const float* __restrict__ coors,
    const float* __restrict__ be2,   // 16
    const float* __restrict__ bc1,   // 64
    const float* __restrict__ Wc2,   // 64
    const float* __restrict__ bc2,   // 1
    float* __restrict__ out_coors)   // NG x 3
{
    __shared__ __align__(16) float sA[NPB*EHP];
    __shared__ float sWc2[64];
    __shared__ float sbc1[64];
    __shared__ float sbe2[16];
    __shared__ float sfe[NPB*32*9];
    __shared__ float srel[NPB*32*3];
    __shared__ int   sj[NPB*32];

    const int tid  = threadIdx.x;
    const int w    = tid >> 5;
    const int lane = tid & 31;

    {
        const int g0 = blockIdx.x * NPB;
        for (int i = tid; i < NPB*EHP; i += 128)
            sA[i] = d_A[(size_t)g0*EHP + i];
    }
    if (tid < 64) sWc2[tid] = Wc2[tid];
    if (tid < 64) sbc1[tid] = bc1[tid];
    if (tid < 16) sbe2[tid] = be2[tid];

    const int g = blockIdx.x * NPB + w;
    const int boff = g & ~(NPTS - 1);
    const float cix = coors[g*3+0], ciy = coors[g*3+1], ciz = coors[g*3+2];
    const float bc2v = bc2[0];

    {
        const int j = d_idx[g*KNN_K + lane];
        sj[w*32 + lane] = j;
        const int r = boff + j;
        float rx = cix - coors[r*3+0];
        float ry = ciy - coors[r*3+1];
        float rz = ciz - coors[r*3+2];
        float d  = rx*rx + ry*ry + rz*rz;
        float* fp = sfe + (w*32 + lane)*9;
        float s, c;
        sincosf(d,        &s, &c); fp[0] = s; fp[4] = c;
        sincosf(d*0.5f,   &s, &c); fp[1] = s; fp[5] = c;
        sincosf(d*0.25f,  &s, &c); fp[2] = s; fp[6] = c;
        sincosf(d*0.125f, &s, &c); fp[3] = s; fp[7] = c;
        fp[8] = d;
        float* rp = srel + (w*32 + lane)*3;
        rp[0] = rx; rp[1] = ry; rp[2] = rz;
    }
    __syncthreads();

    const int q  = lane & 3;
    const int E1 = lane >> 2;
    const int E2 = E1 + 8;
    unsigned long long ms0 = 0ull, ms1 = 0ull;
    float cax = 0.f, cay = 0.f, caz = 0.f;

    const float be2a = sbe2[2*q],   be2b = sbe2[2*q+1];
    const float be2c = sbe2[2*q+8], be2d = sbe2[2*q+9];

    #pragma unroll 1
    for (int grp = 0; grp < 2; grp++) {
        const int e0 = grp*16;
        unsigned feA0, feA1, feA2, feA3;
        {
            const float* f1 = sfe + (w*32 + e0 + E1)*9;
            const float* f2 = sfe + (w*32 + e0 + E2)*9;
            const int fq = 4*q;
            float a0 = (fq   < 9) ? f1[fq]   : 0.f;
            float a1 = (fq+1 < 9) ? f1[fq+1] : 0.f;
            float a2 = (fq+2 < 9) ? f1[fq+2] : 0.f;
            float a3 = (fq+3 < 9) ? f1[fq+3] : 0.f;
            float b0 = (fq   < 9) ? f2[fq]   : 0.f;
            float b1 = (fq+1 < 9) ? f2[fq+1] : 0.f;
            float b2 = (fq+2 < 9) ? f2[fq+2] : 0.f;
            float b3 = (fq+3 < 9) ? f2[fq+3] : 0.f;
            feA0 = cvtbf2(a0, a1);
            feA1 = cvtbf2(b0, b1);
            feA2 = cvtbf2(a2, a3);
            feA3 = cvtbf2(b2, b3);
        }
        const float* pB1 = d_Bf + (size_t)(boff + sj[w*32 + e0 + E1]) * EHP;
        const float* pB2 = d_Bf + (size_t)(boff + sj[w*32 + e0 + E2]) * EHP;

        float m00=0.f,m01=0.f,m02=0.f,m03=0.f;
        float m10=0.f,m11=0.f,m12=0.f,m13=0.f;

        ulonglong2 bb1 = *(const ulonglong2*)(pB1 + 4*q);
        ulonglong2 bb2 = *(const ulonglong2*)(pB2 + 4*q);

        #pragma unroll 1
        for (int s = 0; s < NSTEP; s++) {
            const int ka = s*16 + 4*q;
            ulonglong2 nb1, nb2;
            if (s < NSTEP-1) {
                nb1 = *(const ulonglong2*)(pB1 + ka + 16);
                nb2 = *(const ulonglong2*)(pB2 + ka + 16);
            }
            const ulonglong2 aa = *(const ulonglong2*)(sA + w*EHP + ka);
            float d00,d01,d02,d03, u00,u01,u02,u03;
            { unsigned long long t = add2(aa.x, bb1.x); upk2(t, d00, d01); }
            { unsigned long long t = add2(aa.x, bb2.x); upk2(t, d02, d03); }
            { unsigned long long t = add2(aa.y, bb1.y); upk2(t, u00, u01); }
            { unsigned long long t = add2(aa.y, bb2.y); upk2(t, u02, u03); }
            const uint4 wf = *(const uint4*)&d_W1ffrag[(s*32 + lane)*4];
            MMA_BF16(d00,d01,d02,d03, feA0,feA1,feA2,feA3, wf.x, wf.y);
            MMA_BF16(u00,u01,u02,u03, feA0,feA1,feA2,feA3, wf.z, wf.w);
            const unsigned a0 = cvtbf2(silu_fast(d00), silu_fast(d01));
            const unsigned a1 = cvtbf2(silu_fast(d02), silu_fast(d03));
            const unsigned a2 = cvtbf2(silu_fast(u00), silu_fast(u01));
            const unsigned a3 = cvtbf2(silu_fast(u02), silu_fast(u03));
            const uint4 bf = *(const uint4*)&d_We2frag[(s*32 + lane)*4];
            MMA_BF16(m00,m01,m02,m03, a0,a1,a2,a3, bf.x, bf.y);
            MMA_BF16(m10,m11,m12,m13, a0,a1,a2,a3, bf.z, bf.w);
            bb1 = nb1; bb2 = nb2;
        }

        const float s00 = siluf(m00 + be2a), s01 = siluf(m01 + be2b);
        const float s02 = siluf(m02 + be2a), s03 = siluf(m03 + be2b);
        const float s10 = siluf(m10 + be2c), s11 = siluf(m11 + be2d);
        const float s12 = siluf(m12 + be2c), s13 = siluf(m13 + be2d);

        ms0 = add2(ms0, add2(pk2(s00, s01), pk2(s02, s03)));
        ms1 = add2(ms1, add2(pk2(s10, s11), pk2(s12, s13)));

        const unsigned am0 = cvtbf2(s00, s01);
        const unsigned am1 = cvtbf2(s02, s03);
        const unsigned am2 = cvtbf2(s10, s11);
        const unsigned am3 = cvtbf2(s12, s13);
        float wE1 = 0.f, wE2 = 0.f;
        #pragma unroll
        for (int nt = 0; nt < 8; nt++) {
            const uint2 wb = d_Wc1frag[nt*32 + lane];
            float h0=0.f,h1=0.f,h2=0.f,h3=0.f;
            MMA_BF16(h0,h1,h2,h3, am0,am1,am2,am3, wb.x, wb.y);
            const float2 bb = *(const float2*)(sbc1 + nt*8 + 2*q);
            const float2 cc = *(const float2*)(sWc2 + nt*8 + 2*q);
            wE1 += silu_fast(h0 + bb.x)*cc.x + silu_fast(h1 + bb.y)*cc.y;
            wE2 += silu_fast(h2 + bb.x)*cc.x + silu_fast(h3 + bb.y)*cc.y;
        }
        unsigned long long wp = pk2(wE1, wE2);
        wp = add2(wp, __shfl_xor_sync(0xffffffffu, wp, 1));
        wp = add2(wp, __shfl_xor_sync(0xffffffffu, wp, 2));
        float we1, we2; upk2(wp, we1, we2);
        we1 += bc2v; we2 += bc2v;
        if (q == 0) {
            const float* r1 = srel + (w*32 + e0 + E1)*3;
            const float* r2 = srel + (w*32 + e0 + E2)*3;
            cax += we1*r1[0] + we2*r2[0];
            cay += we1*r1[1] + we2*r2[1];
            caz += we1*r1[2] + we2*r2[2];
        }
    }

    ms0 = add2(ms0, __shfl_xor_sync(0xffffffffu, ms0, 4));
    ms0 = add2(ms0, __shfl_xor_sync(0xffffffffu, ms0, 8));
    ms0 = add2(ms0, __shfl_xor_sync(0xffffffffu, ms0, 16));
    ms1 = add2(ms1, __shfl_xor_sync(0xffffffffu, ms1, 4));
    ms1 = add2(ms1, __shfl_xor_sync(0xffffffffu, ms1, 8));
    ms1 = add2(ms1, __shfl_xor_sync(0xffffffffu, ms1, 16));
    if (lane < 4) {
        float lo, hi;
        upk2(ms0, lo, hi);
        d_mi[(size_t)g*MDIM + 2*lane    ] = lo;
        d_mi[(size_t)g*MDIM + 2*lane + 1] = hi;
        upk2(ms1, lo, hi);
        d_mi[(size_t)g*MDIM + 2*lane + 8] = lo;
        d_mi[(size_t)g*MDIM + 2*lane + 9] = hi;
    }

    cax += __shfl_xor_sync(0xffffffffu, cax, 4);
    cax += __shfl_xor_sync(0xffffffffu, cax, 8);
    cax += __shfl_xor_sync(0xffffffffu, cax, 16);
    cay += __shfl_xor_sync(0xffffffffu, cay, 4);
    cay += __shfl_xor_sync(0xffffffffu, cay, 8);
    cay += __shfl_xor_sync(0xffffffffu, cay, 16);
    caz += __shfl_xor_sync(0xffffffffu, caz, 4);
    caz += __shfl_xor_sync(0xffffffffu, caz, 8);
    caz += __shfl_xor_sync(0xffffffffu, caz, 16);
    if (lane == 0) {
        out_coors[g*3+0] = cax + cix;
        out_coors[g*3+1] = cay + ciy;
        out_coors[g*3+2] = caz + ciz;
    }
}

// build concat(feats, m_i) -> d_nodein
__global__ void nodein_kernel(const float* __restrict__ feats)
{
    int i = blockIdx.x * blockDim.x + threadIdx.x;
    if (i < NG * NODE_IN) {
        int gg = i / NODE_IN, c = i - gg * NODE_IN;
        d_nodein[i] = (c < DIM) ? feats[(size_t)gg*DIM + c]
                                : d_mi[(size_t)gg*MDIM + (c - DIM)];
    }
}

// ------------------------------ launch ----------------------------------------
extern "C" void kernel_launch(void* const* d_in, const int* in_sizes, int n_in,
                              void* d_out, int out_size)
{
    const float* feats = (const float*)d_in[0];
    const float* coors = (const float*)d_in[1];
    const float* We1   = (const float*)d_in[2];
    const float* be1   = (const float*)d_in[3];
    const float* We2   = (const float*)d_in[4];
    const float* be2   = (const float*)d_in[5];
    const float* Wc1   = (const float*)d_in[6];
    const float* bc1   = (const float*)d_in[7];
    const float* Wc2   = (const float*)d_in[8];
    const float* bc2   = (const float*)d_in[9];
    const float* Wn1   = (const float*)d_in[10];
    const float* bn1   = (const float*)d_in[11];
    const float* Wn2   = (const float*)d_in[12];
    const float* bn2   = (const float*)d_in[13];

    float* out_nodes = (float*)d_out;
    float* out_coors = out_nodes + (size_t)NG * DIM;

    float *pA, *pB, *pNI, *pH;
    unsigned *pW0, *pW1, *pW2, *pW3;
    cudaGetSymbolAddress((void**)&pA,  d_A);
    cudaGetSymbolAddress((void**)&pB,  d_Bf);
    cudaGetSymbolAddress((void**)&pNI, d_nodein);
    cudaGetSymbolAddress((void**)&pH,  d_h);
    cudaGetSymbolAddress((void**)&pW0, d_WP0);
    cudaGetSymbolAddress((void**)&pW1, d_WP1);
    cudaGetSymbolAddress((void**)&pW2, d_WP2);
    cudaGetSymbolAddress((void**)&pW3, d_WP3);

    // 0. one prep launch for all packed tables
    prep_kernel<<<(576*64 + 255)/256, 256>>>(We1, We2, Wc1, Wn1, Wn2);

    // 1. KNN
    knn_kernel<<<NG, 256>>>(coors);

    // 2. A and B in one z-batched launch
    {
        dim3 grid((EH + 63) / 64, NG / 128, 2);
        gemm_mma<<<grid, 256>>>(feats, DIM, pW0, pW1, 64, be1, nullptr, 0,
                                pA, pB, EHP, NG, EH, DIM, 0);
    }

    // 3. fused edge kernel: m_i + coors_out
    edge_kernel<<<NG / NPB, 128>>>(coors, be2, bc1, Wc2, bc2, out_coors);

    // 4. node MLP
    nodein_kernel<<<(NG*NODE_IN + 255)/256, 256>>>(feats);
    {
        dim3 g1(NODE_H / 64, NG / 128, 1);
        gemm_mma<<<g1, 256>>>(pNI, NODE_IN, pW2, nullptr, 80, bn1, nullptr, 0,
                              pH, nullptr, NODE_H, NG, NODE_H, NODE_IN, 1);
        dim3 g2(DIM / 64, NG / 128, 1);
        gemm_mma<<<g2, 256>>>(pH, NODE_H, pW3, nullptr, 128, bn2, feats, DIM,
                              out_nodes, nullptr, DIM, NG, DIM, NODE_H, 0);
    }
}